// round 10
// baseline (speedup 1.0000x reference)
#include <cuda_runtime.h>
#include <cuda_bf16.h>
#include <cuda_fp16.h>
#include <mma.h>
#include <cstdint>
#include <cstddef>

using namespace nvcuda;

#define FDIM 128
#define KDIM 64
#define CDIM 256
#define MNBR 12
#define NMAX 100000
#define NEDGE (NMAX * MNBR)

typedef __nv_bfloat16 bf16;

__device__ float  g_Pself[(size_t)NMAX * CDIM];
__device__ float  g_Pnbr [(size_t)NMAX * CDIM];
__device__ __half g_gatedh[(size_t)NEDGE * CDIM];
__device__ float  g_nbrsum[(size_t)NMAX * FDIM];
__device__ int    g_idx32[NEDGE];
__device__ float  g_sum1[CDIM], g_sq1[CDIM], g_scale1[CDIM], g_shift1[CDIM];
__device__ float  g_sum2[FDIM], g_sq2[FDIM], g_scale2[FDIM], g_shift2[FDIM];
__device__ int    g_idx_is64;

__device__ __forceinline__ void split2(float a, float b, uint32_t& hi, uint32_t& lo) {
    __nv_bfloat162 H, L;
    H.x = __float2bfloat16(a); H.y = __float2bfloat16(b);
    L.x = __float2bfloat16(a - __bfloat162float(H.x));
    L.y = __float2bfloat16(b - __bfloat162float(H.y));
    hi = *(uint32_t*)&H; lo = *(uint32_t*)&L;
}

__global__ void k_zero(const int* __restrict__ idx32) {
    int t = threadIdx.x;
    if (t < CDIM) { g_sum1[t] = 0.f; g_sq1[t] = 0.f; }
    if (t < FDIM) { g_sum2[t] = 0.f; g_sq2[t] = 0.f; }
    if (t == 0) {
        int nz = 0;
        #pragma unroll 4
        for (int i = 1; i < 128; i += 2) nz |= (idx32[i] != 0);
        g_idx_is64 = nz ? 0 : 1;
    }
}
__global__ void k_idx(const void* __restrict__ raw, int total) {
    int i = blockIdx.x * blockDim.x + threadIdx.x;
    if (i < total)
        g_idx32[i] = g_idx_is64 ? (int)((const long long*)raw)[i] : ((const int*)raw)[i];
}

// ---- K1: projection GEMMs. grid (ceil(N/128), 2). part 0 -> Pself, 1 -> Pnbr.
// A: 128 atoms x 128K (hi/lo, ldim 136). B: W[:, part*128 +k] col-major K x 256 (ldim 136).
#define PLD 136
__global__ void __launch_bounds__(256) k_proj(const float* __restrict__ atom,
                                              const float* __restrict__ W, int N) {
    extern __shared__ __align__(16) char smem[];
    bf16* sAh = (bf16*)smem;                 // 128*136
    bf16* sAl = sAh + 128 * PLD;
    bf16* sWh = sAl + 128 * PLD;             // 256*136 (col-major: (k,n) at n*PLD+k)
    bf16* sWl = sWh + 256 * PLD;
    const int tid = threadIdx.x, wid = tid >> 5;
    const int part = blockIdx.y, n0 = blockIdx.x * 128;

    {   // A rows
        int row = tid >> 1, kh = tid & 1, n = n0 + row;
        #pragma unroll
        for (int i = 0; i < 16; i++) {
            float4 v = (n < N) ? *(const float4*)(atom + (size_t)n * FDIM + kh * 64 + i * 4)
                               : make_float4(0.f, 0.f, 0.f, 0.f);
            int k = kh * 64 + i * 4;
            uint32_t h0, l0, h1, l1;
            split2(v.x, v.y, h0, l0); split2(v.z, v.w, h1, l1);
            *(uint32_t*)(sAh + row * PLD + k)     = h0;
            *(uint32_t*)(sAh + row * PLD + k + 2) = h1;
            *(uint32_t*)(sAl + row * PLD + k)     = l0;
            *(uint32_t*)(sAl + row * PLD + k + 2) = l1;
        }
    }
    {   // W rows (channel c = tid)
        const float* wp = W + (size_t)tid * 320 + part * 128;
        #pragma unroll
        for (int i = 0; i < 32; i++) {
            float4 v = *(const float4*)(wp + i * 4);
            int k = i * 4;
            uint32_t h0, l0, h1, l1;
            split2(v.x, v.y, h0, l0); split2(v.z, v.w, h1, l1);
            *(uint32_t*)(sWh + tid * PLD + k)     = h0;
            *(uint32_t*)(sWh + tid * PLD + k + 2) = h1;
            *(uint32_t*)(sWl + tid * PLD + k)     = l0;
            *(uint32_t*)(sWl + tid * PLD + k + 2) = l1;
        }
    }
    __syncthreads();

    if (n0 + wid * 16 >= N) return;
    float* outp = (part ? g_Pnbr : g_Pself) + (size_t)(n0 + wid * 16) * CDIM;
    wmma::fragment<wmma::matrix_a, 16, 16, 16, bf16, wmma::row_major> ah, al;
    wmma::fragment<wmma::matrix_b, 16, 16, 16, bf16, wmma::col_major> bh, bl;
    wmma::fragment<wmma::accumulator, 16, 16, 16, float> acc;
    for (int nt = 0; nt < 16; nt++) {
        wmma::fill_fragment(acc, 0.f);
        #pragma unroll
        for (int ks = 0; ks < 8; ks++) {
            wmma::load_matrix_sync(ah, sAh + wid * 16 * PLD + ks * 16, PLD);
            wmma::load_matrix_sync(al, sAl + wid * 16 * PLD + ks * 16, PLD);
            wmma::load_matrix_sync(bh, sWh + nt * 16 * PLD + ks * 16, PLD);
            wmma::load_matrix_sync(bl, sWl + nt * 16 * PLD + ks * 16, PLD);
            wmma::mma_sync(acc, ah, bh, acc);
            wmma::mma_sync(acc, ah, bl, acc);
            wmma::mma_sync(acc, al, bh, acc);
        }
        wmma::store_matrix_sync(outp + nt * 16, acc, CDIM, wmma::mem_row_major);
    }
}

// ---- K2: edge GEMM + gather + assemble gated + BN1 stats. grid ceil(Ntot/128).
#define ELD 72
#define SLD 68
__global__ void __launch_bounds__(256) k_edge(const float* __restrict__ nbr,
                                              const float* __restrict__ W,
                                              const float* __restrict__ bias,
                                              int N, int Ntot) {
    extern __shared__ __align__(16) char smem[];
    bf16*  sAh = (bf16*)smem;                    // 128*72
    bf16*  sAl = sAh + 128 * ELD;
    bf16*  sWh = sAl + 128 * ELD;                // 256*72 col-major
    bf16*  sWl = sWh + 256 * ELD;
    float* stg = (float*)(sWl + 256 * ELD);      // 128*68
    float* sB  = stg + 128 * SLD;                // 256
    int*   sIdx = (int*)(sB + 256);              // 128
    const int tid = threadIdx.x, wid = tid >> 5;
    const int e0 = blockIdx.x * 128;

    if (tid < 128) sIdx[tid] = (e0 + tid < Ntot) ? g_idx32[e0 + tid] : 0;
    sB[tid] = bias[tid];
    {   // A: edge features
        int row = tid >> 1, kh = tid & 1, e = e0 + row;
        #pragma unroll
        for (int i = 0; i < 8; i++) {
            float4 v = (e < Ntot) ? *(const float4*)(nbr + (size_t)e * KDIM + kh * 32 + i * 4)
                                  : make_float4(0.f, 0.f, 0.f, 0.f);
            int k = kh * 32 + i * 4;
            uint32_t h0, l0, h1, l1;
            split2(v.x, v.y, h0, l0); split2(v.z, v.w, h1, l1);
            *(uint32_t*)(sAh + row * ELD + k)     = h0;
            *(uint32_t*)(sAh + row * ELD + k + 2) = h1;
            *(uint32_t*)(sAl + row * ELD + k)     = l0;
            *(uint32_t*)(sAl + row * ELD + k + 2) = l1;
        }
    }
    {   // W3 rows
        const float* wp = W + (size_t)tid * 320 + 256;
        #pragma unroll
        for (int i = 0; i < 16; i++) {
            float4 v = *(const float4*)(wp + i * 4);
            int k = i * 4;
            uint32_t h0, l0, h1, l1;
            split2(v.x, v.y, h0, l0); split2(v.z, v.w, h1, l1);
            *(uint32_t*)(sWh + tid * ELD + k)     = h0;
            *(uint32_t*)(sWh + tid * ELD + k + 2) = h1;
            *(uint32_t*)(sWl + tid * ELD + k)     = l0;
            *(uint32_t*)(sWl + tid * ELD + k + 2) = l1;
        }
    }
    __syncthreads();

    wmma::fragment<wmma::matrix_a, 16, 16, 16, bf16, wmma::row_major> ah, al;
    wmma::fragment<wmma::matrix_b, 16, 16, 16, bf16, wmma::col_major> bh, bl;
    wmma::fragment<wmma::accumulator, 16, 16, 16, float> acc[4];

    const int colc = tid & 63;     // this thread's fixed staging column
    #pragma unroll 1
    for (int chunk = 0; chunk < 4; chunk++) {
        #pragma unroll
        for (int nt = 0; nt < 4; nt++) wmma::fill_fragment(acc[nt], 0.f);
        #pragma unroll
        for (int ks = 0; ks < 4; ks++) {
            wmma::load_matrix_sync(ah, sAh + wid * 16 * ELD + ks * 16, ELD);
            wmma::load_matrix_sync(al, sAl + wid * 16 * ELD + ks * 16, ELD);
            #pragma unroll
            for (int nt = 0; nt < 4; nt++) {
                const int nc = (chunk * 64 + nt * 16) * ELD + ks * 16;
                wmma::load_matrix_sync(bh, sWh + nc, ELD);
                wmma::load_matrix_sync(bl, sWl + nc, ELD);
                wmma::mma_sync(acc[nt], ah, bh, acc[nt]);
                wmma::mma_sync(acc[nt], ah, bl, acc[nt]);
                wmma::mma_sync(acc[nt], al, bh, acc[nt]);
            }
        }
        #pragma unroll
        for (int nt = 0; nt < 4; nt++)
            wmma::store_matrix_sync(stg + wid * 16 * SLD + nt * 16, acc[nt], SLD,
                                    wmma::mem_row_major);
        __syncthreads();

        // epilogue: stg + Pself + Pnbr + bias -> fp16 gated; BN1 stats inline
        const int c = chunk * 64 + colc;
        const float bc = sB[c];
        float ls = 0.f, lq = 0.f;
        #pragma unroll
        for (int j = 0; j < 32; j++) {
            int row = (tid >> 6) + j * 4;
            int e = e0 + row;
            if (e < Ntot) {
                int a = e / MNBR; if (a >= N) a = N - 1;
                float val = stg[row * SLD + colc]
                          + g_Pself[(size_t)a * CDIM + c]
                          + g_Pnbr[(size_t)sIdx[row] * CDIM + c] + bc;
                __half h = __float2half_rn(val);
                g_gatedh[(size_t)e * CDIM + c] = h;
                float f = __half2float(h);
                ls += f; lq += f * f;
            }
        }
        atomicAdd(&g_sum1[c], ls);
        atomicAdd(&g_sq1[c], lq);
        __syncthreads();
    }
}

__global__ void k_fin1(const float* __restrict__ gm, const float* __restrict__ bt, float ic) {
    int c = threadIdx.x;
    float mean = g_sum1[c] * ic, var = g_sq1[c] * ic - mean * mean;
    float sc = gm[c] * rsqrtf(var + 1e-5f);
    g_scale1[c] = sc; g_shift1[c] = bt[c] - mean * sc;
}
__global__ void __launch_bounds__(256) k_sum(int N) {
    const int p = threadIdx.x & 63, g = threadIdx.x >> 6, n0 = blockIdx.x * 32;
    const float scf0 = g_scale1[2 * p], shf0 = g_shift1[2 * p];
    const float scf1 = g_scale1[2 * p + 1], shf1 = g_shift1[2 * p + 1];
    const float scc0 = g_scale1[128 + 2 * p], shc0 = g_shift1[128 + 2 * p];
    const float scc1 = g_scale1[128 + 2 * p + 1], shc1 = g_shift1[128 + 2 * p + 1];
    float ls0 = 0.f, lq0 = 0.f, ls1 = 0.f, lq1 = 0.f;
    for (int a = g; a < 32; a += 4) {
        const int n = n0 + a;
        if (n >= N) break;
        const __half* row = g_gatedh + (size_t)n * MNBR * CDIM;
        float a0 = 0.f, a1 = 0.f;
        #pragma unroll
        for (int m = 0; m < MNBR; m++) {
            float2 hf = __half22float2(*(const __half2*)(row + (size_t)m * CDIM + 2 * p));
            float2 hc = __half22float2(*(const __half2*)(row + (size_t)m * CDIM + 128 + 2 * p));
            float gf0 = hf.x * scf0 + shf0, gf1 = hf.y * scf1 + shf1;
            float gc0 = hc.x * scc0 + shc0, gc1 = hc.y * scc1 + shc1;
            a0 += (1.f / (1.f + expf(-gf0))) * (gc0 > 0.f ? gc0 : 0.f);
            a1 += (1.f / (1.f + expf(-gf1))) * (gc1 > 0.f ? gc1 : 0.f);
        }
        *(float2*)(g_nbrsum + (size_t)n * FDIM + 2 * p) = make_float2(a0, a1);
        ls0 += a0; lq0 += a0 * a0; ls1 += a1; lq1 += a1 * a1;
    }
    atomicAdd(&g_sum2[2 * p], ls0);     atomicAdd(&g_sq2[2 * p], lq0);
    atomicAdd(&g_sum2[2 * p + 1], ls1); atomicAdd(&g_sq2[2 * p + 1], lq1);
}
__global__ void k_fin2(const float* __restrict__ gm, const float* __restrict__ bt, float ic) {
    int c = threadIdx.x;
    float mean = g_sum2[c] * ic, var = g_sq2[c] * ic - mean * mean;
    float sc = gm[c] * rsqrtf(var + 1e-5f);
    g_scale2[c] = sc; g_shift2[c] = bt[c] - mean * sc;
}
__global__ void k_out(const float* __restrict__ atom, float* __restrict__ out, int total) {
    int i = blockIdx.x * blockDim.x + threadIdx.x;
    if (i < total) {
        int f = i & 127;
        float v = atom[i] + g_nbrsum[i] * g_scale2[f] + g_shift2[f];
        out[i] = v > 0.f ? v : 0.f;
    }
}

extern "C" void kernel_launch(void* const* d_in, const int* in_sizes, int n_in,
                              void* d_out, int out_size) {
    const float* atom = (const float*)d_in[0];
    const float* nbr  = (const float*)d_in[1];
    const void*  idx  = d_in[2];
    const float* W    = (const float*)d_in[3];
    const float* b    = (const float*)d_in[4];
    const float* g1   = (const float*)d_in[5];
    const float* b1   = (const float*)d_in[6];
    const float* g2   = (const float*)d_in[7];
    const float* b2   = (const float*)d_in[8];
    float* out = (float*)d_out;
    const int N = in_sizes[0] / FDIM;
    const int Ntot = N * MNBR;

    const int smP = (2 * 128 * PLD + 2 * 256 * PLD) * 2;                 // 208896
    const int smE = (2 * 128 * ELD + 2 * 256 * ELD) * 2
                  + (128 * SLD + 256) * 4 + 128 * 4;                      // 146944
    static int configured = 0;
    if (!configured) {
        cudaFuncSetAttribute(k_proj, cudaFuncAttributeMaxDynamicSharedMemorySize, smP);
        cudaFuncSetAttribute(k_edge, cudaFuncAttributeMaxDynamicSharedMemorySize, smE);
        configured = 1;
    }

    k_zero<<<1, 256>>>((const int*)idx);                           // 1
    k_idx<<<(Ntot + 255) / 256, 256>>>(idx, Ntot);                 // 2
    dim3 gp((N + 127) / 128, 2);
    k_proj<<<gp, 256, smP>>>(atom, W, N);                          // 3
    k_edge<<<(Ntot + 127) / 128, 256, smE>>>(nbr, W, b, N, Ntot);  // 4 <- ncu slot
    k_fin1<<<1, CDIM>>>(g1, b1, 1.f / ((float)N * (float)MNBR));   // 5
    k_sum<<<(N + 31) / 32, 256>>>(N);                              // 6
    k_fin2<<<1, FDIM>>>(g2, b2, 1.f / (float)N);                   // 7
    k_out<<<((size_t)N * FDIM + 255) / 256, 256>>>(atom, out, N * FDIM);
}

// round 11
// speedup vs baseline: 2.0963x; 2.0963x over previous
#include <cuda_runtime.h>
#include <cuda_bf16.h>
#include <cuda_fp16.h>
#include <mma.h>
#include <cstdint>
#include <cstddef>

using namespace nvcuda;

#define FDIM 128
#define KDIM 64
#define CDIM 256
#define MNBR 12
#define NMAX 100000
#define NEDGE (NMAX * MNBR)

typedef __nv_bfloat16 bf16;

__device__ float  g_Pself[(size_t)NMAX * CDIM];
__device__ float  g_Pnbr [(size_t)NMAX * CDIM];
__device__ __half g_gatedh[(size_t)NEDGE * CDIM];
__device__ float  g_nbrsum[(size_t)NMAX * FDIM];
__device__ int    g_idx32[NEDGE];
__device__ float  g_sum1[CDIM], g_sq1[CDIM], g_scale1[CDIM], g_shift1[CDIM];
__device__ float  g_sum2[FDIM], g_sq2[FDIM], g_scale2[FDIM], g_shift2[FDIM];
__device__ int    g_idx_is64;

__device__ __forceinline__ void split2(float a, float b, uint32_t& hi, uint32_t& lo) {
    __nv_bfloat162 H, L;
    H.x = __float2bfloat16(a); H.y = __float2bfloat16(b);
    L.x = __float2bfloat16(a - __bfloat162float(H.x));
    L.y = __float2bfloat16(b - __bfloat162float(H.y));
    hi = *(uint32_t*)&H; lo = *(uint32_t*)&L;
}

__global__ void k_zero(const int* __restrict__ idx32) {
    int t = threadIdx.x;
    if (t < CDIM) { g_sum1[t] = 0.f; g_sq1[t] = 0.f; }
    if (t < FDIM) { g_sum2[t] = 0.f; g_sq2[t] = 0.f; }
    if (t == 0) {
        int nz = 0;
        #pragma unroll 4
        for (int i = 1; i < 128; i += 2) nz |= (idx32[i] != 0);
        g_idx_is64 = nz ? 0 : 1;
    }
}
__global__ void k_idx(const void* __restrict__ raw, int total) {
    int i = blockIdx.x * blockDim.x + threadIdx.x;
    if (i < total)
        g_idx32[i] = g_idx_is64 ? (int)((const long long*)raw)[i] : ((const int*)raw)[i];
}

// ---- K1: projection GEMMs. grid (ceil(N/128), 2). part 0 -> Pself, 1 -> Pnbr.
#define PLD 136
__global__ void __launch_bounds__(256) k_proj(const float* __restrict__ atom,
                                              const float* __restrict__ W, int N) {
    extern __shared__ __align__(16) char smem[];
    bf16* sAh = (bf16*)smem;
    bf16* sAl = sAh + 128 * PLD;
    bf16* sWh = sAl + 128 * PLD;
    bf16* sWl = sWh + 256 * PLD;
    const int tid = threadIdx.x, wid = tid >> 5;
    const int part = blockIdx.y, n0 = blockIdx.x * 128;

    {   // A rows (128 x 128 K)
        int row = tid >> 1, kh = tid & 1, n = n0 + row;
        #pragma unroll
        for (int i = 0; i < 16; i++) {
            float4 v = (n < N) ? *(const float4*)(atom + (size_t)n * FDIM + kh * 64 + i * 4)
                               : make_float4(0.f, 0.f, 0.f, 0.f);
            int k = kh * 64 + i * 4;
            uint32_t h0, l0, h1, l1;
            split2(v.x, v.y, h0, l0); split2(v.z, v.w, h1, l1);
            *(uint32_t*)(sAh + row * PLD + k)     = h0;
            *(uint32_t*)(sAh + row * PLD + k + 2) = h1;
            *(uint32_t*)(sAl + row * PLD + k)     = l0;
            *(uint32_t*)(sAl + row * PLD + k + 2) = l1;
        }
    }
    {   // W rows (channel c = tid, 128 K)
        const float* wp = W + (size_t)tid * 320 + part * 128;
        #pragma unroll
        for (int i = 0; i < 32; i++) {
            float4 v = *(const float4*)(wp + i * 4);
            int k = i * 4;
            uint32_t h0, l0, h1, l1;
            split2(v.x, v.y, h0, l0); split2(v.z, v.w, h1, l1);
            *(uint32_t*)(sWh + tid * PLD + k)     = h0;
            *(uint32_t*)(sWh + tid * PLD + k + 2) = h1;
            *(uint32_t*)(sWl + tid * PLD + k)     = l0;
            *(uint32_t*)(sWl + tid * PLD + k + 2) = l1;
        }
    }
    __syncthreads();

    if (n0 + wid * 16 >= N) return;
    float* outp = (part ? g_Pnbr : g_Pself) + (size_t)(n0 + wid * 16) * CDIM;
    wmma::fragment<wmma::matrix_a, 16, 16, 16, bf16, wmma::row_major> ah[8], al[8];
    wmma::fragment<wmma::matrix_b, 16, 16, 16, bf16, wmma::col_major> bh, bl;
    wmma::fragment<wmma::accumulator, 16, 16, 16, float> acc;
    #pragma unroll
    for (int ks = 0; ks < 8; ks++) {
        wmma::load_matrix_sync(ah[ks], sAh + wid * 16 * PLD + ks * 16, PLD);
        wmma::load_matrix_sync(al[ks], sAl + wid * 16 * PLD + ks * 16, PLD);
    }
    #pragma unroll 1
    for (int nt = 0; nt < 16; nt++) {
        wmma::fill_fragment(acc, 0.f);
        #pragma unroll
        for (int ks = 0; ks < 8; ks++) {
            wmma::load_matrix_sync(bh, sWh + nt * 16 * PLD + ks * 16, PLD);
            wmma::load_matrix_sync(bl, sWl + nt * 16 * PLD + ks * 16, PLD);
            wmma::mma_sync(acc, ah[ks], bh, acc);
            wmma::mma_sync(acc, ah[ks], bl, acc);
            wmma::mma_sync(acc, al[ks], bh, acc);
        }
        wmma::store_matrix_sync(outp + nt * 16, acc, CDIM, wmma::mem_row_major);
    }
}

// ---- K2: edge GEMM + staged gathers + assemble gated + BN1 stats.
// grid Ntot/128 (exact: 1.2M/128 = 9375). 128 edges x 256 ch per CTA.
#define ELD 72
#define SLD 68
// smem byte offsets
#define OAH 0
#define OAL 18432
#define OWH 36864
#define OWL 73728
#define OST 110592
#define OSG 145408
#define OPS 180224
#define OBI 192512
#define OIX 193536
#define SME 194048
__global__ void __launch_bounds__(256) k_edge(const float* __restrict__ nbr,
                                              const float* __restrict__ W,
                                              const float* __restrict__ bias,
                                              int N, int Ntot) {
    extern __shared__ __align__(16) char smem[];
    bf16*  sAh = (bf16*)(smem + OAH);
    bf16*  sAl = (bf16*)(smem + OAL);
    bf16*  sWh = (bf16*)(smem + OWH);
    bf16*  sWl = (bf16*)(smem + OWL);
    float* stg = (float*)(smem + OST);   // 128 x 68
    float* sG  = (float*)(smem + OSG);   // 128 x 68 (gathered Pnbr chunk)
    float* sPs = (float*)(smem + OPS);   // 12 x 256
    float* sB  = (float*)(smem + OBI);
    int*   sIdx = (int*)(smem + OIX);
    const int tid = threadIdx.x, wid = tid >> 5;
    const int e0 = blockIdx.x * 128;
    const int a0 = e0 / MNBR;

    if (tid < 128) sIdx[tid] = (e0 + tid < Ntot) ? g_idx32[e0 + tid] : 0;
    sB[tid] = bias[tid];
    {   // A: edge features (128 x 64)
        int row = tid >> 1, kh = tid & 1, e = e0 + row;
        #pragma unroll
        for (int i = 0; i < 8; i++) {
            float4 v = (e < Ntot) ? *(const float4*)(nbr + (size_t)e * KDIM + kh * 32 + i * 4)
                                  : make_float4(0.f, 0.f, 0.f, 0.f);
            int k = kh * 32 + i * 4;
            uint32_t h0, l0, h1, l1;
            split2(v.x, v.y, h0, l0); split2(v.z, v.w, h1, l1);
            *(uint32_t*)(sAh + row * ELD + k)     = h0;
            *(uint32_t*)(sAh + row * ELD + k + 2) = h1;
            *(uint32_t*)(sAl + row * ELD + k)     = l0;
            *(uint32_t*)(sAl + row * ELD + k + 2) = l1;
        }
    }
    {   // W3 rows (c = tid, 64 K)
        const float* wp = W + (size_t)tid * 320 + 256;
        #pragma unroll
        for (int i = 0; i < 16; i++) {
            float4 v = *(const float4*)(wp + i * 4);
            int k = i * 4;
            uint32_t h0, l0, h1, l1;
            split2(v.x, v.y, h0, l0); split2(v.z, v.w, h1, l1);
            *(uint32_t*)(sWh + tid * ELD + k)     = h0;
            *(uint32_t*)(sWh + tid * ELD + k + 2) = h1;
            *(uint32_t*)(sWl + tid * ELD + k)     = l0;
            *(uint32_t*)(sWl + tid * ELD + k + 2) = l1;
        }
    }
    // P_self rows for this tile (<= 12 distinct atoms), coalesced
    for (int q = tid; q < 12 * 64; q += 256) {
        int r = q >> 6, i = q & 63;
        int a = a0 + r; if (a >= N) a = N - 1;
        ((float4*)sPs)[r * 64 + i] = ((const float4*)(g_Pself + (size_t)a * CDIM))[i];
    }
    __syncthreads();

    // A fragments once per tile
    wmma::fragment<wmma::matrix_a, 16, 16, 16, bf16, wmma::row_major> ah[4], al[4];
    wmma::fragment<wmma::matrix_b, 16, 16, 16, bf16, wmma::col_major> bh, bl;
    #pragma unroll
    for (int ks = 0; ks < 4; ks++) {
        wmma::load_matrix_sync(ah[ks], sAh + wid * 16 * ELD + ks * 16, ELD);
        wmma::load_matrix_sync(al[ks], sAl + wid * 16 * ELD + ks * 16, ELD);
    }
    const int gr = tid >> 1, gs = tid & 1;          // gather: row, 32-ch segment
    const size_t gbase = (size_t)sIdx[gr] * CDIM;
    const int c64 = tid & 63, grp = tid >> 6;

    #pragma unroll 1
    for (int chunk = 0; chunk < 4; chunk++) {
        // issue coalesced Pnbr gathers for this chunk (hidden under MMA)
        float4 gv[8];
        const float4* gp = (const float4*)(g_Pnbr + gbase + chunk * 64 + gs * 32);
        #pragma unroll
        for (int i = 0; i < 8; i++) gv[i] = gp[i];

        wmma::fragment<wmma::accumulator, 16, 16, 16, float> acc[4];
        #pragma unroll
        for (int nt = 0; nt < 4; nt++) wmma::fill_fragment(acc[nt], 0.f);
        #pragma unroll
        for (int ks = 0; ks < 4; ks++) {
            #pragma unroll
            for (int nt = 0; nt < 4; nt++) {
                const int nc = (chunk * 64 + nt * 16) * ELD + ks * 16;
                wmma::load_matrix_sync(bh, sWh + nc, ELD);
                wmma::load_matrix_sync(bl, sWl + nc, ELD);
                wmma::mma_sync(acc[nt], ah[ks], bh, acc[nt]);
                wmma::mma_sync(acc[nt], ah[ks], bl, acc[nt]);
                wmma::mma_sync(acc[nt], al[ks], bh, acc[nt]);
            }
        }
        // land gathers + GEMM results in smem
        #pragma unroll
        for (int i = 0; i < 8; i++) ((float4*)sG)[gr * 17 + gs * 8 + i] = gv[i];
        #pragma unroll
        for (int nt = 0; nt < 4; nt++)
            wmma::store_matrix_sync(stg + wid * 16 * SLD + nt * 16, acc[nt], SLD,
                                    wmma::mem_row_major);
        __syncthreads();

        // epilogue: all reads from smem, coalesced fp16 stores
        const int c = chunk * 64 + c64;
        const float bc = sB[c];
        float ls = 0.f, lq = 0.f;
        #pragma unroll
        for (int j = 0; j < 32; j++) {
            int r = grp * 32 + j;
            int e = e0 + r;
            int rm = e / MNBR - a0;
            float val = stg[r * SLD + c64] + sG[r * SLD + c64]
                      + sPs[rm * 256 + c] + bc;
            __half h = __float2half_rn(val);
            float f = __half2float(h);
            if (e < Ntot) {
                g_gatedh[(size_t)e * CDIM + c] = h;
                ls += f; lq += f * f;
            }
        }
        atomicAdd(&g_sum1[c], ls);
        atomicAdd(&g_sq1[c], lq);
        __syncthreads();
    }
}

__global__ void k_fin1(const float* __restrict__ gm, const float* __restrict__ bt, float ic) {
    int c = threadIdx.x;
    float mean = g_sum1[c] * ic, var = g_sq1[c] * ic - mean * mean;
    float sc = gm[c] * rsqrtf(var + 1e-5f);
    g_scale1[c] = sc; g_shift1[c] = bt[c] - mean * sc;
}
__global__ void __launch_bounds__(256) k_sum(int N) {
    const int p = threadIdx.x & 63, g = threadIdx.x >> 6, n0 = blockIdx.x * 32;
    const float scf0 = g_scale1[2 * p], shf0 = g_shift1[2 * p];
    const float scf1 = g_scale1[2 * p + 1], shf1 = g_shift1[2 * p + 1];
    const float scc0 = g_scale1[128 + 2 * p], shc0 = g_shift1[128 + 2 * p];
    const float scc1 = g_scale1[128 + 2 * p + 1], shc1 = g_shift1[128 + 2 * p + 1];
    float ls0 = 0.f, lq0 = 0.f, ls1 = 0.f, lq1 = 0.f;
    for (int a = g; a < 32; a += 4) {
        const int n = n0 + a;
        if (n >= N) break;
        const __half* row = g_gatedh + (size_t)n * MNBR * CDIM;
        float a0 = 0.f, a1 = 0.f;
        #pragma unroll
        for (int m = 0; m < MNBR; m++) {
            float2 hf = __half22float2(*(const __half2*)(row + (size_t)m * CDIM + 2 * p));
            float2 hc = __half22float2(*(const __half2*)(row + (size_t)m * CDIM + 128 + 2 * p));
            float gf0 = hf.x * scf0 + shf0, gf1 = hf.y * scf1 + shf1;
            float gc0 = hc.x * scc0 + shc0, gc1 = hc.y * scc1 + shc1;
            a0 += (1.f / (1.f + expf(-gf0))) * (gc0 > 0.f ? gc0 : 0.f);
            a1 += (1.f / (1.f + expf(-gf1))) * (gc1 > 0.f ? gc1 : 0.f);
        }
        *(float2*)(g_nbrsum + (size_t)n * FDIM + 2 * p) = make_float2(a0, a1);
        ls0 += a0; lq0 += a0 * a0; ls1 += a1; lq1 += a1 * a1;
    }
    atomicAdd(&g_sum2[2 * p], ls0);     atomicAdd(&g_sq2[2 * p], lq0);
    atomicAdd(&g_sum2[2 * p + 1], ls1); atomicAdd(&g_sq2[2 * p + 1], lq1);
}
__global__ void k_fin2(const float* __restrict__ gm, const float* __restrict__ bt, float ic) {
    int c = threadIdx.x;
    float mean = g_sum2[c] * ic, var = g_sq2[c] * ic - mean * mean;
    float sc = gm[c] * rsqrtf(var + 1e-5f);
    g_scale2[c] = sc; g_shift2[c] = bt[c] - mean * sc;
}
__global__ void k_out(const float* __restrict__ atom, float* __restrict__ out, int total) {
    int i = blockIdx.x * blockDim.x + threadIdx.x;
    if (i < total) {
        int f = i & 127;
        float v = atom[i] + g_nbrsum[i] * g_scale2[f] + g_shift2[f];
        out[i] = v > 0.f ? v : 0.f;
    }
}

extern "C" void kernel_launch(void* const* d_in, const int* in_sizes, int n_in,
                              void* d_out, int out_size) {
    const float* atom = (const float*)d_in[0];
    const float* nbr  = (const float*)d_in[1];
    const void*  idx  = d_in[2];
    const float* W    = (const float*)d_in[3];
    const float* b    = (const float*)d_in[4];
    const float* g1   = (const float*)d_in[5];
    const float* b1   = (const float*)d_in[6];
    const float* g2   = (const float*)d_in[7];
    const float* b2   = (const float*)d_in[8];
    float* out = (float*)d_out;
    const int N = in_sizes[0] / FDIM;
    const int Ntot = N * MNBR;

    const int smP = (2 * 128 * PLD + 2 * 256 * PLD) * 2;   // 208896
    static int configured = 0;
    if (!configured) {
        cudaFuncSetAttribute(k_proj, cudaFuncAttributeMaxDynamicSharedMemorySize, smP);
        cudaFuncSetAttribute(k_edge, cudaFuncAttributeMaxDynamicSharedMemorySize, SME);
        configured = 1;
    }

    k_zero<<<1, 256>>>((const int*)idx);                           // 1
    k_idx<<<(Ntot + 255) / 256, 256>>>(idx, Ntot);                 // 2
    dim3 gp((N + 127) / 128, 2);
    k_proj<<<gp, 256, smP>>>(atom, W, N);                          // 3
    k_edge<<<(Ntot + 127) / 128, 256, SME>>>(nbr, W, b, N, Ntot);  // 4 <- ncu slot
    k_fin1<<<1, CDIM>>>(g1, b1, 1.f / ((float)N * (float)MNBR));   // 5
    k_sum<<<(N + 31) / 32, 256>>>(N);                              // 6
    k_fin2<<<1, FDIM>>>(g2, b2, 1.f / (float)N);                   // 7
    k_out<<<((size_t)N * FDIM + 255) / 256, 256>>>(atom, out, N * FDIM);
}

// round 12
// speedup vs baseline: 2.1118x; 1.0074x over previous
#include <cuda_runtime.h>
#include <cuda_bf16.h>
#include <cuda_fp16.h>
#include <mma.h>
#include <cstdint>
#include <cstddef>

using namespace nvcuda;

#define FDIM 128
#define KDIM 64
#define CDIM 256
#define MNBR 12
#define NMAX 100000
#define NEDGE (NMAX * MNBR)

typedef __nv_bfloat16 bf16;

__device__ float  g_Pself[(size_t)NMAX * CDIM];
__device__ float  g_Pnbr [(size_t)NMAX * CDIM];
__device__ __half g_gatedh[(size_t)NEDGE * CDIM];
__device__ float  g_nbrsum[(size_t)NMAX * FDIM];
__device__ int    g_idx32[NEDGE];
__device__ float  g_sum1[CDIM], g_sq1[CDIM], g_scale1[CDIM], g_shift1[CDIM];
__device__ float  g_sum2[FDIM], g_sq2[FDIM], g_scale2[FDIM], g_shift2[FDIM];
__device__ int    g_idx_is64;

__device__ __forceinline__ void split2(float a, float b, uint32_t& hi, uint32_t& lo) {
    __nv_bfloat162 H, L;
    H.x = __float2bfloat16(a); H.y = __float2bfloat16(b);
    L.x = __float2bfloat16(a - __bfloat162float(H.x));
    L.y = __float2bfloat16(b - __bfloat162float(H.y));
    hi = *(uint32_t*)&H; lo = *(uint32_t*)&L;
}

__global__ void k_zero(const int* __restrict__ idx32) {
    int t = threadIdx.x;
    if (t < CDIM) { g_sum1[t] = 0.f; g_sq1[t] = 0.f; }
    if (t < FDIM) { g_sum2[t] = 0.f; g_sq2[t] = 0.f; }
    if (t == 0) {
        int nz = 0;
        #pragma unroll 4
        for (int i = 1; i < 128; i += 2) nz |= (idx32[i] != 0);
        g_idx_is64 = nz ? 0 : 1;
    }
}
__global__ void k_idx(const void* __restrict__ raw, int total) {
    int i = blockIdx.x * blockDim.x + threadIdx.x;
    if (i < total)
        g_idx32[i] = g_idx_is64 ? (int)((const long long*)raw)[i] : ((const int*)raw)[i];
}

// ---- K1: projection GEMMs. grid (ceil(N/128), 2). 512 thr; warp = (atile, nhalf).
#define PLD 136
__global__ void __launch_bounds__(512) k_proj(const float* __restrict__ atom,
                                              const float* __restrict__ W, int N) {
    extern __shared__ __align__(16) char smem[];
    bf16* sAh = (bf16*)smem;                     // 128 x 136
    bf16* sAl = sAh + 128 * PLD;
    bf16* sWh = sAl + 128 * PLD;                 // 256 x 136
    bf16* sWl = sWh + 256 * PLD;
    const int tid = threadIdx.x, wid = tid >> 5;
    const int part = blockIdx.y, n0 = blockIdx.x * 128;

    {   // A: row = tid/4, quarter = tid&3 (32 K each)
        int row = tid >> 2, q = tid & 3, n = n0 + row;
        #pragma unroll
        for (int i = 0; i < 8; i++) {
            float4 v = (n < N) ? *(const float4*)(atom + (size_t)n * FDIM + q * 32 + i * 4)
                               : make_float4(0.f, 0.f, 0.f, 0.f);
            int k = q * 32 + i * 4;
            uint32_t h0, l0, h1, l1;
            split2(v.x, v.y, h0, l0); split2(v.z, v.w, h1, l1);
            *(uint32_t*)(sAh + row * PLD + k)     = h0;
            *(uint32_t*)(sAh + row * PLD + k + 2) = h1;
            *(uint32_t*)(sAl + row * PLD + k)     = l0;
            *(uint32_t*)(sAl + row * PLD + k + 2) = l1;
        }
    }
    {   // W: row = tid/2, half = tid&1 (64 K each)
        int wr = tid >> 1, hf = tid & 1;
        const float* wp = W + (size_t)wr * 320 + part * 128 + hf * 64;
        #pragma unroll
        for (int i = 0; i < 16; i++) {
            float4 v = *(const float4*)(wp + i * 4);
            int k = hf * 64 + i * 4;
            uint32_t h0, l0, h1, l1;
            split2(v.x, v.y, h0, l0); split2(v.z, v.w, h1, l1);
            *(uint32_t*)(sWh + wr * PLD + k)     = h0;
            *(uint32_t*)(sWh + wr * PLD + k + 2) = h1;
            *(uint32_t*)(sWl + wr * PLD + k)     = l0;
            *(uint32_t*)(sWl + wr * PLD + k + 2) = l1;
        }
    }
    __syncthreads();

    const int atile = wid >> 1, nh = wid & 1;
    const int nbase = n0 + atile * 16;
    if (nbase >= N) return;
    float* outp = (part ? g_Pnbr : g_Pself) + (size_t)nbase * CDIM + nh * 128;

    wmma::fragment<wmma::matrix_a, 16, 16, 16, bf16, wmma::row_major> ah[8], al;
    wmma::fragment<wmma::matrix_b, 16, 16, 16, bf16, wmma::col_major> bh, bl;
    wmma::fragment<wmma::accumulator, 16, 16, 16, float> acc;
    #pragma unroll
    for (int ks = 0; ks < 8; ks++)
        wmma::load_matrix_sync(ah[ks], sAh + atile * 16 * PLD + ks * 16, PLD);
    #pragma unroll 1
    for (int nt = 0; nt < 8; nt++) {
        wmma::fill_fragment(acc, 0.f);
        #pragma unroll
        for (int ks = 0; ks < 8; ks++) {
            const int nc = (nh * 128 + nt * 16) * PLD + ks * 16;
            wmma::load_matrix_sync(bh, sWh + nc, PLD);
            wmma::load_matrix_sync(bl, sWl + nc, PLD);
            wmma::load_matrix_sync(al, sAl + atile * 16 * PLD + ks * 16, PLD);
            wmma::mma_sync(acc, ah[ks], bh, acc);
            wmma::mma_sync(acc, ah[ks], bl, acc);
            wmma::mma_sync(acc, al, bh, acc);
        }
        wmma::store_matrix_sync(outp + nt * 16, acc, CDIM, wmma::mem_row_major);
    }
}

// ---- K2: edge GEMM + gathers + gated + BN1 stats. 512 thr, 256-edge tiles.
// Warp-independent after setup: warp owns 16 edges; no block sync in chunk loop.
#define ELD 72
#define SLD 68
#define OWH 73728
#define OWL 110592
#define OBI 147456
#define OIX 148480
#define SME 149504
__global__ void __launch_bounds__(512) k_edge(const float* __restrict__ nbr,
                                              const float* __restrict__ W,
                                              const float* __restrict__ bias,
                                              int N, int Ntot) {
    extern __shared__ __align__(16) char smem[];
    bf16*  sAh = (bf16*)smem;                 // 256 x 72 (reused as stg after frags)
    bf16*  sAl = sAh + 256 * ELD;
    bf16*  sWh = (bf16*)(smem + OWH);         // 256 x 72
    bf16*  sWl = (bf16*)(smem + OWL);
    float* sB  = (float*)(smem + OBI);
    int*   sIdx = (int*)(smem + OIX);
    const int tid = threadIdx.x, wid = tid >> 5, lane = tid & 31;
    const int e0 = blockIdx.x * 256;

    if (tid < 256) {
        sIdx[tid] = (e0 + tid < Ntot) ? g_idx32[e0 + tid] : 0;
        sB[tid] = bias[tid];
    }
    {   // A: row = tid/2, half = tid&1 (32 K each)
        int row = tid >> 1, kh = tid & 1, e = e0 + row;
        #pragma unroll
        for (int i = 0; i < 8; i++) {
            float4 v = (e < Ntot) ? *(const float4*)(nbr + (size_t)e * KDIM + kh * 32 + i * 4)
                                  : make_float4(0.f, 0.f, 0.f, 0.f);
            int k = kh * 32 + i * 4;
            uint32_t h0, l0, h1, l1;
            split2(v.x, v.y, h0, l0); split2(v.z, v.w, h1, l1);
            *(uint32_t*)(sAh + row * ELD + k)     = h0;
            *(uint32_t*)(sAh + row * ELD + k + 2) = h1;
            *(uint32_t*)(sAl + row * ELD + k)     = l0;
            *(uint32_t*)(sAl + row * ELD + k + 2) = l1;
        }
    }
    {   // W3: row = tid/2, half = tid&1
        int wr = tid >> 1, kh = tid & 1;
        const float* wp = W + (size_t)wr * 320 + 256 + kh * 32;
        #pragma unroll
        for (int i = 0; i < 8; i++) {
            float4 v = *(const float4*)(wp + i * 4);
            int k = kh * 32 + i * 4;
            uint32_t h0, l0, h1, l1;
            split2(v.x, v.y, h0, l0); split2(v.z, v.w, h1, l1);
            *(uint32_t*)(sWh + wr * ELD + k)     = h0;
            *(uint32_t*)(sWh + wr * ELD + k + 2) = h1;
            *(uint32_t*)(sWl + wr * ELD + k)     = l0;
            *(uint32_t*)(sWl + wr * ELD + k + 2) = l1;
        }
    }
    __syncthreads();

    wmma::fragment<wmma::matrix_a, 16, 16, 16, bf16, wmma::row_major> ah[4], al[4];
    wmma::fragment<wmma::matrix_b, 16, 16, 16, bf16, wmma::col_major> bh, bl;
    #pragma unroll
    for (int ks = 0; ks < 4; ks++) {
        wmma::load_matrix_sync(ah[ks], sAh + wid * 16 * ELD + ks * 16, ELD);
        wmma::load_matrix_sync(al[ks], sAl + wid * 16 * ELD + ks * 16, ELD);
    }
    __syncthreads();   // A region now reusable as per-warp staging

    float* stg = (float*)(smem + wid * (16 * SLD * 4));   // 4352 B per warp
    const int er0 = e0 + wid * 16;
    const int c2 = lane * 2;

    #pragma unroll 1
    for (int chunk = 0; chunk < 4; chunk++) {
        wmma::fragment<wmma::accumulator, 16, 16, 16, float> acc[4];
        #pragma unroll
        for (int nt = 0; nt < 4; nt++) wmma::fill_fragment(acc[nt], 0.f);
        #pragma unroll
        for (int ks = 0; ks < 4; ks++) {
            #pragma unroll
            for (int nt = 0; nt < 4; nt++) {
                const int nc = (chunk * 64 + nt * 16) * ELD + ks * 16;
                wmma::load_matrix_sync(bh, sWh + nc, ELD);
                wmma::load_matrix_sync(bl, sWl + nc, ELD);
                wmma::mma_sync(acc[nt], ah[ks], bh, acc[nt]);
                wmma::mma_sync(acc[nt], ah[ks], bl, acc[nt]);
                wmma::mma_sync(acc[nt], al[ks], bh, acc[nt]);
            }
        }
        #pragma unroll
        for (int nt = 0; nt < 4; nt++)
            wmma::store_matrix_sync(stg + nt * 16, acc[nt], SLD, wmma::mem_row_major);
        __syncwarp();

        const int c = chunk * 64 + c2;
        const float bc0 = sB[c], bc1 = sB[c + 1];
        float s0 = 0.f, q0 = 0.f, s1 = 0.f, q1 = 0.f;
        #pragma unroll 1
        for (int b = 0; b < 2; b++) {
            float2 pn[8], ps[8];
            #pragma unroll
            for (int j = 0; j < 8; j++) {
                int r = b * 8 + j;
                int id = sIdx[wid * 16 + r];
                pn[j] = *(const float2*)(g_Pnbr + (size_t)id * CDIM + c);
                int a = (er0 + r) / MNBR; if (a >= N) a = N - 1;
                ps[j] = *(const float2*)(g_Pself + (size_t)a * CDIM + c);
            }
            #pragma unroll
            for (int j = 0; j < 8; j++) {
                int r = b * 8 + j, e = er0 + r;
                float v0 = stg[r * SLD + c2]     + pn[j].x + ps[j].x + bc0;
                float v1 = stg[r * SLD + c2 + 1] + pn[j].y + ps[j].y + bc1;
                __half2 h2 = __floats2half2_rn(v0, v1);
                if (e < Ntot) {
                    *(__half2*)(g_gatedh + (size_t)e * CDIM + c) = h2;
                    float2 f = __half22float2(h2);
                    s0 += f.x; q0 += f.x * f.x; s1 += f.y; q1 += f.y * f.y;
                }
            }
        }
        atomicAdd(&g_sum1[c], s0);     atomicAdd(&g_sq1[c], q0);
        atomicAdd(&g_sum1[c + 1], s1); atomicAdd(&g_sq1[c + 1], q1);
        __syncwarp();
    }
}

__global__ void k_fin1(const float* __restrict__ gm, const float* __restrict__ bt, float ic) {
    int c = threadIdx.x;
    float mean = g_sum1[c] * ic, var = g_sq1[c] * ic - mean * mean;
    float sc = gm[c] * rsqrtf(var + 1e-5f);
    g_scale1[c] = sc; g_shift1[c] = bt[c] - mean * sc;
}
__global__ void __launch_bounds__(256) k_sum(int N) {
    const int p = threadIdx.x & 63, g = threadIdx.x >> 6, n0 = blockIdx.x * 32;
    const float scf0 = g_scale1[2 * p], shf0 = g_shift1[2 * p];
    const float scf1 = g_scale1[2 * p + 1], shf1 = g_shift1[2 * p + 1];
    const float scc0 = g_scale1[128 + 2 * p], shc0 = g_shift1[128 + 2 * p];
    const float scc1 = g_scale1[128 + 2 * p + 1], shc1 = g_shift1[128 + 2 * p + 1];
    float ls0 = 0.f, lq0 = 0.f, ls1 = 0.f, lq1 = 0.f;
    for (int a = g; a < 32; a += 4) {
        const int n = n0 + a;
        if (n >= N) break;
        const __half* row = g_gatedh + (size_t)n * MNBR * CDIM;
        float a0 = 0.f, a1 = 0.f;
        #pragma unroll
        for (int m = 0; m < MNBR; m++) {
            float2 hf = __half22float2(*(const __half2*)(row + (size_t)m * CDIM + 2 * p));
            float2 hc = __half22float2(*(const __half2*)(row + (size_t)m * CDIM + 128 + 2 * p));
            float gf0 = hf.x * scf0 + shf0, gf1 = hf.y * scf1 + shf1;
            float gc0 = hc.x * scc0 + shc0, gc1 = hc.y * scc1 + shc1;
            a0 += (1.f / (1.f + expf(-gf0))) * (gc0 > 0.f ? gc0 : 0.f);
            a1 += (1.f / (1.f + expf(-gf1))) * (gc1 > 0.f ? gc1 : 0.f);
        }
        *(float2*)(g_nbrsum + (size_t)n * FDIM + 2 * p) = make_float2(a0, a1);
        ls0 += a0; lq0 += a0 * a0; ls1 += a1; lq1 += a1 * a1;
    }
    atomicAdd(&g_sum2[2 * p], ls0);     atomicAdd(&g_sq2[2 * p], lq0);
    atomicAdd(&g_sum2[2 * p + 1], ls1); atomicAdd(&g_sq2[2 * p + 1], lq1);
}
__global__ void k_fin2(const float* __restrict__ gm, const float* __restrict__ bt, float ic) {
    int c = threadIdx.x;
    float mean = g_sum2[c] * ic, var = g_sq2[c] * ic - mean * mean;
    float sc = gm[c] * rsqrtf(var + 1e-5f);
    g_scale2[c] = sc; g_shift2[c] = bt[c] - mean * sc;
}
__global__ void k_out(const float* __restrict__ atom, float* __restrict__ out, int total) {
    int i = blockIdx.x * blockDim.x + threadIdx.x;
    if (i < total) {
        int f = i & 127;
        float v = atom[i] + g_nbrsum[i] * g_scale2[f] + g_shift2[f];
        out[i] = v > 0.f ? v : 0.f;
    }
}

extern "C" void kernel_launch(void* const* d_in, const int* in_sizes, int n_in,
                              void* d_out, int out_size) {
    const float* atom = (const float*)d_in[0];
    const float* nbr  = (const float*)d_in[1];
    const void*  idx  = d_in[2];
    const float* W    = (const float*)d_in[3];
    const float* b    = (const float*)d_in[4];
    const float* g1   = (const float*)d_in[5];
    const float* b1   = (const float*)d_in[6];
    const float* g2   = (const float*)d_in[7];
    const float* b2   = (const float*)d_in[8];
    float* out = (float*)d_out;
    const int N = in_sizes[0] / FDIM;
    const int Ntot = N * MNBR;

    const int smP = (2 * 128 * PLD + 2 * 256 * PLD) * 2;   // 208896
    static int configured = 0;
    if (!configured) {
        cudaFuncSetAttribute(k_proj, cudaFuncAttributeMaxDynamicSharedMemorySize, smP);
        cudaFuncSetAttribute(k_edge, cudaFuncAttributeMaxDynamicSharedMemorySize, SME);
        configured = 1;
    }

    k_zero<<<1, 256>>>((const int*)idx);                           // 1
    k_idx<<<(Ntot + 255) / 256, 256>>>(idx, Ntot);                 // 2
    dim3 gp((N + 127) / 128, 2);
    k_proj<<<gp, 512, smP>>>(atom, W, N);                          // 3
    k_edge<<<(Ntot + 255) / 256, 512, SME>>>(nbr, W, b, N, Ntot);  // 4 <- ncu slot
    k_fin1<<<1, CDIM>>>(g1, b1, 1.f / ((float)N * (float)MNBR));   // 5
    k_sum<<<(N + 31) / 32, 256>>>(N);                              // 6
    k_fin2<<<1, FDIM>>>(g2, b2, 1.f / (float)N);                   // 7
    k_out<<<((size_t)N * FDIM + 255) / 256, 256>>>(atom, out, N * FDIM);
}